// round 16
// baseline (speedup 1.0000x reference)
#include <cuda_runtime.h>
#include <cuda_bf16.h>
#include <math.h>
#include <stdint.h>

// Problem shape (fixed by reference: B=4096, D=512)
#define NB 4096
#define ND 512

// GEMM tiling
#define BM 128
#define BN 128
#define BK 64
#define NCHUNK (ND / BK)       // 8 k-chunks
#define GTHREADS 256
#define PITCH 72               // smem row pitch in bf16 (144B) -> conflict-free ldmatrix
#define ROWB (PITCH * 2)       // 144 bytes per smem row
#define STAGE_A (BM * ROWB)    // 18432 B
#define STAGE_B (BN * ROWB)    // 18432 B
#define SM_DYN (2 * (STAGE_A + STAGE_B))   // 73728 B dynamic smem

#define NBLK (NB / BM)         // 32 tile blocks per dimension
#define NEG_BIG (-1e30f)

// ---------------- scratch (device globals; no allocation allowed) ----------
__device__ __nv_bfloat16 g_a[(size_t)NB * ND];   // bf16 ftir
__device__ __nv_bfloat16 g_b[(size_t)NB * ND];   // bf16 raman
__device__ float g_rp_m[NBLK * NB];              // row partial max   [colblk][row]
__device__ float g_rp_s[NBLK * NB];              // row partial sum
__device__ float g_cp_m[NBLK * NB];              // col partial max   [rowblk][col]
__device__ float g_cp_s[NBLK * NB];              // col partial sum
__device__ float g_diag[NB];
__device__ double g_part[32];
__device__ int    g_ticket;                      // zero-init; self-resetting

// ---------------------------------------------------------------------------
// helpers
// ---------------------------------------------------------------------------
__device__ __forceinline__ uint32_t smem_u32(const void* p) {
    uint32_t a;
    asm("{ .reg .u64 t; cvta.to.shared.u64 t, %1; cvt.u32.u64 %0, t; }"
        : "=r"(a) : "l"(p));
    return a;
}

#define CP_ASYNC16(dst_u32, src_ptr) \
    asm volatile("cp.async.cg.shared.global [%0], [%1], 16;" \
        :: "r"(dst_u32), "l"(src_ptr) : "memory")
#define CP_COMMIT() asm volatile("cp.async.commit_group;" ::: "memory")
#define CP_WAIT(n)  asm volatile("cp.async.wait_group %0;" :: "n"(n) : "memory")

#define LDMATRIX_X4(r0, r1, r2, r3, addr) \
    asm volatile("ldmatrix.sync.aligned.m8n8.x4.shared.b16 {%0,%1,%2,%3}, [%4];" \
        : "=r"(r0), "=r"(r1), "=r"(r2), "=r"(r3) : "r"(addr))

#define MMA_16816(d, a, b) \
    asm volatile("mma.sync.aligned.m16n8k16.row.col.f32.bf16.bf16.f32 " \
        "{%0,%1,%2,%3}, {%4,%5,%6,%7}, {%8,%9}, {%0,%1,%2,%3};" \
        : "+f"((d)[0]), "+f"((d)[1]), "+f"((d)[2]), "+f"((d)[3]) \
        : "r"((a)[0]), "r"((a)[1]), "r"((a)[2]), "r"((a)[3]), \
          "r"((b)[0]), "r"((b)[1]))

// ---------------------------------------------------------------------------
// K0: fp32 -> bf16 conversion of both inputs
// ---------------------------------------------------------------------------
__global__ __launch_bounds__(256)
void convert_kernel(const float* __restrict__ srcA, const float* __restrict__ srcB)
{
    const float* src = blockIdx.y ? srcB : srcA;
    __nv_bfloat16* dst = blockIdx.y ? g_b : g_a;
    size_t i = ((size_t)blockIdx.x * 256 + threadIdx.x) * 8;
    float4 v0 = *(const float4*)(src + i);
    float4 v1 = *(const float4*)(src + i + 4);
    __nv_bfloat162 o[4];
    o[0] = __float22bfloat162_rn(make_float2(v0.x, v0.y));
    o[1] = __float22bfloat162_rn(make_float2(v0.z, v0.w));
    o[2] = __float22bfloat162_rn(make_float2(v1.x, v1.y));
    o[3] = __float22bfloat162_rn(make_float2(v1.z, v1.w));
    *(uint4*)(dst + i) = *(const uint4*)o;
}

// ---------------------------------------------------------------------------
// K1: fused GEMM + split-softmax partials.
// 128x128 logits tile in registers; BK=64 double-buffered cp.async pipeline
// with ONE __syncthreads per k-iteration.
// ---------------------------------------------------------------------------
__global__ __launch_bounds__(GTHREADS, 2)
void gemm_fused_kernel(const float* __restrict__ log_tau)
{
    extern __shared__ char dyn[];
    __shared__ float sm_rm[2][BM], sm_rs[2][BM];   // [wn][row_local]
    __shared__ float sm_cm[4][BN], sm_cs[4][BN];   // [wm][col_local]

    const int tid  = threadIdx.x;
    const int wid  = tid >> 5;
    const int lane = tid & 31;
    const int wm   = wid & 3;     // warp M index (0..3)
    const int wn   = wid >> 2;    // warp N index (0..1)
    const int bx   = blockIdx.x;
    const int by   = blockIdx.y;
    const int row0 = by * BM;
    const int col0 = bx * BN;

    const uint32_t sA0 = smem_u32(dyn);
    const uint32_t sB0 = sA0 + 2 * STAGE_A;

    // producer mapping: 128 rows x 8 segs of 16B; 256 threads -> 4 rows each
    const int pr  = tid >> 3;     // 0..31
    const int seg = tid & 7;      // 0..7

    const uint32_t aoff =
        (uint32_t)((wm * 32 + ((lane >> 3) & 1) * 8 + (lane & 7)) * ROWB
                   + (lane >> 4) * 16);
    const uint32_t boff =
        (uint32_t)((wn * 64 + (lane >> 4) * 8 + (lane & 7)) * ROWB
                   + ((lane >> 3) & 1) * 16);

    float acc[2][8][4];
#pragma unroll
    for (int i = 0; i < 2; ++i)
#pragma unroll
        for (int j = 0; j < 8; ++j)
#pragma unroll
            for (int q = 0; q < 4; ++q) acc[i][j][q] = 0.f;

    // --- prefetch chunk 0
#pragma unroll
    for (int t = 0; t < 4; ++t) {
        const int r = t * 32 + pr;
        CP_ASYNC16(sA0 + r * ROWB + seg * 16,
                   g_a + (size_t)(row0 + r) * ND + seg * 8);
        CP_ASYNC16(sB0 + r * ROWB + seg * 16,
                   g_b + (size_t)(col0 + r) * ND + seg * 8);
    }
    CP_COMMIT();

    for (int c = 0; c < NCHUNK; ++c) {
        const int cur = c & 1;
        CP_WAIT(0);            // loads for chunk c complete
        __syncthreads();       // visible to all; all warps done with buffer cur^1

        if (c + 1 < NCHUNK) {
            const int nxt = cur ^ 1;
            const int k0 = (c + 1) * BK;
            const uint32_t dA = sA0 + nxt * STAGE_A;
            const uint32_t dB = sB0 + nxt * STAGE_B;
#pragma unroll
            for (int t = 0; t < 4; ++t) {
                const int r = t * 32 + pr;
                CP_ASYNC16(dA + r * ROWB + seg * 16,
                           g_a + (size_t)(row0 + r) * ND + k0 + seg * 8);
                CP_ASYNC16(dB + r * ROWB + seg * 16,
                           g_b + (size_t)(col0 + r) * ND + k0 + seg * 8);
            }
            CP_COMMIT();
        }

        const uint32_t bufA = sA0 + cur * STAGE_A + aoff;
        const uint32_t bufB = sB0 + cur * STAGE_B + boff;

#pragma unroll
        for (int ks = 0; ks < 4; ++ks) {        // four k16 steps per 64-chunk
            const uint32_t kb = ks * 32;        // 16 halves = 32 bytes
            uint32_t a[2][4], b[4][4];
#pragma unroll
            for (int mi = 0; mi < 2; ++mi)
                LDMATRIX_X4(a[mi][0], a[mi][1], a[mi][2], a[mi][3],
                            bufA + mi * (16 * ROWB) + kb);
#pragma unroll
            for (int nj = 0; nj < 4; ++nj)
                LDMATRIX_X4(b[nj][0], b[nj][1], b[nj][2], b[nj][3],
                            bufB + nj * (16 * ROWB) + kb);
#pragma unroll
            for (int mi = 0; mi < 2; ++mi)
#pragma unroll
                for (int nj = 0; nj < 4; ++nj) {
                    MMA_16816(acc[mi][nj * 2],     a[mi], &b[nj][0]);
                    MMA_16816(acc[mi][nj * 2 + 1], a[mi], &b[nj][2]);
                }
        }
    }

    // ---------------- fused epilogue ----------------
    const float tau = fminf(expf(log_tau[0]), 100.0f);
#pragma unroll
    for (int mi = 0; mi < 2; ++mi)
#pragma unroll
        for (int nj = 0; nj < 8; ++nj)
#pragma unroll
            for (int q = 0; q < 4; ++q) acc[mi][nj][q] *= tau;

    const int lrow = lane >> 2;
    const int lcol = (lane & 3) * 2;

    // diag extraction (only on diagonal tiles)
    if (bx == by) {
#pragma unroll
        for (int mi = 0; mi < 2; ++mi)
#pragma unroll
            for (int nj = 0; nj < 8; ++nj)
#pragma unroll
                for (int q = 0; q < 4; ++q) {
                    const int rl = wm * 32 + mi * 16 + ((q >> 1) << 3) + lrow;
                    const int cl = wn * 64 + nj * 8 + lcol + (q & 1);
                    if (rl == cl) g_diag[row0 + rl] = acc[mi][nj][q];
                }
    }

    // --- row partials: max+sum over this warp's 64 columns
#pragma unroll
    for (int mi = 0; mi < 2; ++mi)
#pragma unroll
        for (int h = 0; h < 2; ++h) {
            float m = NEG_BIG;
#pragma unroll
            for (int nj = 0; nj < 8; ++nj)
                m = fmaxf(m, fmaxf(acc[mi][nj][h * 2], acc[mi][nj][h * 2 + 1]));
            m = fmaxf(m, __shfl_xor_sync(0xffffffffu, m, 1));
            m = fmaxf(m, __shfl_xor_sync(0xffffffffu, m, 2));
            float s = 0.f;
#pragma unroll
            for (int nj = 0; nj < 8; ++nj)
                s += __expf(acc[mi][nj][h * 2] - m) +
                     __expf(acc[mi][nj][h * 2 + 1] - m);
            s += __shfl_xor_sync(0xffffffffu, s, 1);
            s += __shfl_xor_sync(0xffffffffu, s, 2);
            if ((lane & 3) == 0) {
                const int r = wm * 32 + mi * 16 + h * 8 + lrow;
                sm_rm[wn][r] = m;
                sm_rs[wn][r] = s;
            }
        }

    // --- col partials: max+sum over this warp's 32 rows
#pragma unroll
    for (int nj = 0; nj < 8; ++nj)
#pragma unroll
        for (int cc = 0; cc < 2; ++cc) {
            const float v0 = acc[0][nj][cc], v1 = acc[0][nj][2 + cc];
            const float v2 = acc[1][nj][cc], v3 = acc[1][nj][2 + cc];
            float m = fmaxf(fmaxf(v0, v1), fmaxf(v2, v3));
            m = fmaxf(m, __shfl_xor_sync(0xffffffffu, m, 4));
            m = fmaxf(m, __shfl_xor_sync(0xffffffffu, m, 8));
            m = fmaxf(m, __shfl_xor_sync(0xffffffffu, m, 16));
            float s = __expf(v0 - m) + __expf(v1 - m) +
                      __expf(v2 - m) + __expf(v3 - m);
            s += __shfl_xor_sync(0xffffffffu, s, 4);
            s += __shfl_xor_sync(0xffffffffu, s, 8);
            s += __shfl_xor_sync(0xffffffffu, s, 16);
            if (lane < 4) {
                const int cl = wn * 64 + nj * 8 + (lane & 3) * 2 + cc;
                sm_cm[wm][cl] = m;
                sm_cs[wm][cl] = s;
            }
        }

    __syncthreads();

    if (tid < BM) {
        const float m0 = sm_rm[0][tid], m1 = sm_rm[1][tid];
        const float m = fmaxf(m0, m1);
        const float s = sm_rs[0][tid] * __expf(m0 - m) +
                        sm_rs[1][tid] * __expf(m1 - m);
        g_rp_m[bx * NB + row0 + tid] = m;
        g_rp_s[bx * NB + row0 + tid] = s;

        float cm = NEG_BIG;
#pragma unroll
        for (int w = 0; w < 4; ++w) cm = fmaxf(cm, sm_cm[w][tid]);
        float cs = 0.f;
#pragma unroll
        for (int w = 0; w < 4; ++w) cs += sm_cs[w][tid] * __expf(sm_cm[w][tid] - cm);
        g_cp_m[by * NB + col0 + tid] = cm;
        g_cp_s[by * NB + col0 + tid] = cs;
    }
}

// ---------------------------------------------------------------------------
// K2: combine partials -> LSE -> loss, single kernel (32 blocks; last block
// sums the 32 per-block double partials deterministically).
// ---------------------------------------------------------------------------
__global__ __launch_bounds__(256)
void combine_final_kernel(float* __restrict__ out)
{
    __shared__ double red[256];
    const int b   = blockIdx.x;
    const int t   = threadIdx.x;
    const int dir = b >> 4;                      // 0 = rows, 1 = cols
    const int i   = (b & 15) * 256 + t;

    const float* Pm = dir ? g_cp_m : g_rp_m;
    const float* Ps = dir ? g_cp_s : g_rp_s;

    float m = NEG_BIG;
#pragma unroll
    for (int c = 0; c < NBLK; ++c)
        m = fmaxf(m, Pm[c * NB + i]);
    float s = 0.f;
#pragma unroll
    for (int c = 0; c < NBLK; ++c)
        s += Ps[c * NB + i] * __expf(Pm[c * NB + i] - m);
    const float lse = m + logf(s);

    double term = 0.5 * (double)lse;
    if (dir == 0) term -= (double)g_diag[i];

    red[t] = term;
    __syncthreads();
    for (int k = 128; k > 0; k >>= 1) {
        if (t < k) red[t] += red[t + k];
        __syncthreads();
    }
    if (t == 0) {
        g_part[b] = red[0];
        __threadfence();
        const int done = atomicAdd(&g_ticket, 1);
        if (done == 31) {
            double sum = 0.0;
            volatile double* vp = g_part;
            for (int k = 0; k < 32; ++k) sum += vp[k];
            out[0] = (float)(sum / (double)NB);
            g_ticket = 0;    // reset for next graph replay
        }
    }
}

// ---------------------------------------------------------------------------
extern "C" void kernel_launch(void* const* d_in, const int* in_sizes, int n_in,
                              void* d_out, int out_size)
{
    const float* ftir    = (const float*)d_in[0];   // [4096, 512] f32
    const float* raman   = (const float*)d_in[1];   // [4096, 512] f32
    // d_in[2] = labels (int64) — unused
    const float* log_tau = (const float*)d_in[3];   // scalar f32

    cudaFuncSetAttribute(gemm_fused_kernel,
                         cudaFuncAttributeMaxDynamicSharedMemorySize, SM_DYN);

    convert_kernel<<<dim3(NB * ND / (256 * 8), 2), 256>>>(ftir, raman);
    gemm_fused_kernel<<<dim3(NB / BN, NB / BM), GTHREADS, SM_DYN>>>(log_tau);
    combine_final_kernel<<<32, 256>>>((float*)d_out);
}

// round 17
// speedup vs baseline: 1.0005x; 1.0005x over previous
#include <cuda_runtime.h>
#include <cuda_bf16.h>
#include <math.h>
#include <stdint.h>

// Problem shape (fixed by reference: B=4096, D=512)
#define NB 4096
#define ND 512

// GEMM tiling
#define BM 128
#define BN 128
#define BK 64
#define NCHUNK (ND / BK)       // 8 k-chunks
#define GTHREADS 256
#define PITCH 72               // smem row pitch in bf16 (144B) -> conflict-free ldmatrix
#define ROWB (PITCH * 2)       // 144 bytes per smem row
#define STAGE_A (BM * ROWB)    // 18432 B
#define STAGE_B (BN * ROWB)    // 18432 B
#define SM_DYN (2 * (STAGE_A + STAGE_B))   // 73728 B dynamic smem

#define NBLK (NB / BM)         // 32 tile blocks per dimension
#define NEG_BIG (-1e30f)

// ---------------- scratch (device globals; no allocation allowed) ----------
__device__ __nv_bfloat16 g_a[(size_t)NB * ND];   // bf16 ftir
__device__ __nv_bfloat16 g_b[(size_t)NB * ND];   // bf16 raman
__device__ float g_rp_m[NBLK * NB];              // row partial max   [colblk][row]
__device__ float g_rp_s[NBLK * NB];              // row partial sum
__device__ float g_cp_m[NBLK * NB];              // col partial max   [rowblk][col]
__device__ float g_cp_s[NBLK * NB];              // col partial sum
__device__ float g_diag[NB];
__device__ double g_part[32];
__device__ int    g_ticket;                      // zero-init; self-resetting

// ---------------------------------------------------------------------------
// helpers
// ---------------------------------------------------------------------------
__device__ __forceinline__ uint32_t smem_u32(const void* p) {
    uint32_t a;
    asm("{ .reg .u64 t; cvta.to.shared.u64 t, %1; cvt.u32.u64 %0, t; }"
        : "=r"(a) : "l"(p));
    return a;
}

#define CP_ASYNC16(dst_u32, src_ptr) \
    asm volatile("cp.async.cg.shared.global [%0], [%1], 16;" \
        :: "r"(dst_u32), "l"(src_ptr) : "memory")
#define CP_COMMIT() asm volatile("cp.async.commit_group;" ::: "memory")
#define CP_WAIT(n)  asm volatile("cp.async.wait_group %0;" :: "n"(n) : "memory")

#define LDMATRIX_X4(r0, r1, r2, r3, addr) \
    asm volatile("ldmatrix.sync.aligned.m8n8.x4.shared.b16 {%0,%1,%2,%3}, [%4];" \
        : "=r"(r0), "=r"(r1), "=r"(r2), "=r"(r3) : "r"(addr))

#define MMA_16816(d, a, b) \
    asm volatile("mma.sync.aligned.m16n8k16.row.col.f32.bf16.bf16.f32 " \
        "{%0,%1,%2,%3}, {%4,%5,%6,%7}, {%8,%9}, {%0,%1,%2,%3};" \
        : "+f"((d)[0]), "+f"((d)[1]), "+f"((d)[2]), "+f"((d)[3]) \
        : "r"((a)[0]), "r"((a)[1]), "r"((a)[2]), "r"((a)[3]), \
          "r"((b)[0]), "r"((b)[1]))

// ---------------------------------------------------------------------------
// K0: fp32 -> bf16 conversion of both inputs
// ---------------------------------------------------------------------------
__global__ __launch_bounds__(256)
void convert_kernel(const float* __restrict__ srcA, const float* __restrict__ srcB)
{
    const float* src = blockIdx.y ? srcB : srcA;
    __nv_bfloat16* dst = blockIdx.y ? g_b : g_a;
    size_t i = ((size_t)blockIdx.x * 256 + threadIdx.x) * 8;
    float4 v0 = *(const float4*)(src + i);
    float4 v1 = *(const float4*)(src + i + 4);
    __nv_bfloat162 o[4];
    o[0] = __float22bfloat162_rn(make_float2(v0.x, v0.y));
    o[1] = __float22bfloat162_rn(make_float2(v0.z, v0.w));
    o[2] = __float22bfloat162_rn(make_float2(v1.x, v1.y));
    o[3] = __float22bfloat162_rn(make_float2(v1.z, v1.w));
    *(uint4*)(dst + i) = *(const uint4*)o;
}

// ---------------------------------------------------------------------------
// K1: fused GEMM + split-softmax partials.
// 128x128 logits tile in registers; BK=64 double-buffered cp.async pipeline
// with ONE __syncthreads per k-iteration.
// ---------------------------------------------------------------------------
__global__ __launch_bounds__(GTHREADS, 2)
void gemm_fused_kernel(const float* __restrict__ log_tau)
{
    extern __shared__ char dyn[];
    __shared__ float sm_rm[2][BM], sm_rs[2][BM];   // [wn][row_local]
    __shared__ float sm_cm[4][BN], sm_cs[4][BN];   // [wm][col_local]

    const int tid  = threadIdx.x;
    const int wid  = tid >> 5;
    const int lane = tid & 31;
    const int wm   = wid & 3;     // warp M index (0..3)
    const int wn   = wid >> 2;    // warp N index (0..1)
    const int bx   = blockIdx.x;
    const int by   = blockIdx.y;
    const int row0 = by * BM;
    const int col0 = bx * BN;

    const uint32_t sA0 = smem_u32(dyn);
    const uint32_t sB0 = sA0 + 2 * STAGE_A;

    // producer mapping: 128 rows x 8 segs of 16B; 256 threads -> 4 rows each
    const int pr  = tid >> 3;     // 0..31
    const int seg = tid & 7;      // 0..7

    const uint32_t aoff =
        (uint32_t)((wm * 32 + ((lane >> 3) & 1) * 8 + (lane & 7)) * ROWB
                   + (lane >> 4) * 16);
    const uint32_t boff =
        (uint32_t)((wn * 64 + (lane >> 4) * 8 + (lane & 7)) * ROWB
                   + ((lane >> 3) & 1) * 16);

    float acc[2][8][4];
#pragma unroll
    for (int i = 0; i < 2; ++i)
#pragma unroll
        for (int j = 0; j < 8; ++j)
#pragma unroll
            for (int q = 0; q < 4; ++q) acc[i][j][q] = 0.f;

    // --- prefetch chunk 0
#pragma unroll
    for (int t = 0; t < 4; ++t) {
        const int r = t * 32 + pr;
        CP_ASYNC16(sA0 + r * ROWB + seg * 16,
                   g_a + (size_t)(row0 + r) * ND + seg * 8);
        CP_ASYNC16(sB0 + r * ROWB + seg * 16,
                   g_b + (size_t)(col0 + r) * ND + seg * 8);
    }
    CP_COMMIT();

    for (int c = 0; c < NCHUNK; ++c) {
        const int cur = c & 1;
        CP_WAIT(0);            // loads for chunk c complete
        __syncthreads();       // visible to all; all warps done with buffer cur^1

        if (c + 1 < NCHUNK) {
            const int nxt = cur ^ 1;
            const int k0 = (c + 1) * BK;
            const uint32_t dA = sA0 + nxt * STAGE_A;
            const uint32_t dB = sB0 + nxt * STAGE_B;
#pragma unroll
            for (int t = 0; t < 4; ++t) {
                const int r = t * 32 + pr;
                CP_ASYNC16(dA + r * ROWB + seg * 16,
                           g_a + (size_t)(row0 + r) * ND + k0 + seg * 8);
                CP_ASYNC16(dB + r * ROWB + seg * 16,
                           g_b + (size_t)(col0 + r) * ND + k0 + seg * 8);
            }
            CP_COMMIT();
        }

        const uint32_t bufA = sA0 + cur * STAGE_A + aoff;
        const uint32_t bufB = sB0 + cur * STAGE_B + boff;

#pragma unroll
        for (int ks = 0; ks < 4; ++ks) {        // four k16 steps per 64-chunk
            const uint32_t kb = ks * 32;        // 16 halves = 32 bytes
            uint32_t a[2][4], b[4][4];
#pragma unroll
            for (int mi = 0; mi < 2; ++mi)
                LDMATRIX_X4(a[mi][0], a[mi][1], a[mi][2], a[mi][3],
                            bufA + mi * (16 * ROWB) + kb);
#pragma unroll
            for (int nj = 0; nj < 4; ++nj)
                LDMATRIX_X4(b[nj][0], b[nj][1], b[nj][2], b[nj][3],
                            bufB + nj * (16 * ROWB) + kb);
#pragma unroll
            for (int mi = 0; mi < 2; ++mi)
#pragma unroll
                for (int nj = 0; nj < 4; ++nj) {
                    MMA_16816(acc[mi][nj * 2],     a[mi], &b[nj][0]);
                    MMA_16816(acc[mi][nj * 2 + 1], a[mi], &b[nj][2]);
                }
        }
    }

    // ---------------- fused epilogue ----------------
    const float tau = fminf(expf(log_tau[0]), 100.0f);
#pragma unroll
    for (int mi = 0; mi < 2; ++mi)
#pragma unroll
        for (int nj = 0; nj < 8; ++nj)
#pragma unroll
            for (int q = 0; q < 4; ++q) acc[mi][nj][q] *= tau;

    const int lrow = lane >> 2;
    const int lcol = (lane & 3) * 2;

    // diag extraction (only on diagonal tiles)
    if (bx == by) {
#pragma unroll
        for (int mi = 0; mi < 2; ++mi)
#pragma unroll
            for (int nj = 0; nj < 8; ++nj)
#pragma unroll
                for (int q = 0; q < 4; ++q) {
                    const int rl = wm * 32 + mi * 16 + ((q >> 1) << 3) + lrow;
                    const int cl = wn * 64 + nj * 8 + lcol + (q & 1);
                    if (rl == cl) g_diag[row0 + rl] = acc[mi][nj][q];
                }
    }

    // --- row partials: max+sum over this warp's 64 columns
#pragma unroll
    for (int mi = 0; mi < 2; ++mi)
#pragma unroll
        for (int h = 0; h < 2; ++h) {
            float m = NEG_BIG;
#pragma unroll
            for (int nj = 0; nj < 8; ++nj)
                m = fmaxf(m, fmaxf(acc[mi][nj][h * 2], acc[mi][nj][h * 2 + 1]));
            m = fmaxf(m, __shfl_xor_sync(0xffffffffu, m, 1));
            m = fmaxf(m, __shfl_xor_sync(0xffffffffu, m, 2));
            float s = 0.f;
#pragma unroll
            for (int nj = 0; nj < 8; ++nj)
                s += __expf(acc[mi][nj][h * 2] - m) +
                     __expf(acc[mi][nj][h * 2 + 1] - m);
            s += __shfl_xor_sync(0xffffffffu, s, 1);
            s += __shfl_xor_sync(0xffffffffu, s, 2);
            if ((lane & 3) == 0) {
                const int r = wm * 32 + mi * 16 + h * 8 + lrow;
                sm_rm[wn][r] = m;
                sm_rs[wn][r] = s;
            }
        }

    // --- col partials: max+sum over this warp's 32 rows
#pragma unroll
    for (int nj = 0; nj < 8; ++nj)
#pragma unroll
        for (int cc = 0; cc < 2; ++cc) {
            const float v0 = acc[0][nj][cc], v1 = acc[0][nj][2 + cc];
            const float v2 = acc[1][nj][cc], v3 = acc[1][nj][2 + cc];
            float m = fmaxf(fmaxf(v0, v1), fmaxf(v2, v3));
            m = fmaxf(m, __shfl_xor_sync(0xffffffffu, m, 4));
            m = fmaxf(m, __shfl_xor_sync(0xffffffffu, m, 8));
            m = fmaxf(m, __shfl_xor_sync(0xffffffffu, m, 16));
            float s = __expf(v0 - m) + __expf(v1 - m) +
                      __expf(v2 - m) + __expf(v3 - m);
            s += __shfl_xor_sync(0xffffffffu, s, 4);
            s += __shfl_xor_sync(0xffffffffu, s, 8);
            s += __shfl_xor_sync(0xffffffffu, s, 16);
            if (lane < 4) {
                const int cl = wn * 64 + nj * 8 + (lane & 3) * 2 + cc;
                sm_cm[wm][cl] = m;
                sm_cs[wm][cl] = s;
            }
        }

    __syncthreads();

    if (tid < BM) {
        const float m0 = sm_rm[0][tid], m1 = sm_rm[1][tid];
        const float m = fmaxf(m0, m1);
        const float s = sm_rs[0][tid] * __expf(m0 - m) +
                        sm_rs[1][tid] * __expf(m1 - m);
        g_rp_m[bx * NB + row0 + tid] = m;
        g_rp_s[bx * NB + row0 + tid] = s;

        float cm = NEG_BIG;
#pragma unroll
        for (int w = 0; w < 4; ++w) cm = fmaxf(cm, sm_cm[w][tid]);
        float cs = 0.f;
#pragma unroll
        for (int w = 0; w < 4; ++w) cs += sm_cs[w][tid] * __expf(sm_cm[w][tid] - cm);
        g_cp_m[by * NB + col0 + tid] = cm;
        g_cp_s[by * NB + col0 + tid] = cs;
    }
}

// ---------------------------------------------------------------------------
// K2: combine partials -> LSE -> loss, single kernel (32 blocks; last block
// sums the 32 per-block double partials deterministically).
// ---------------------------------------------------------------------------
__global__ __launch_bounds__(256)
void combine_final_kernel(float* __restrict__ out)
{
    __shared__ double red[256];
    const int b   = blockIdx.x;
    const int t   = threadIdx.x;
    const int dir = b >> 4;                      // 0 = rows, 1 = cols
    const int i   = (b & 15) * 256 + t;

    const float* Pm = dir ? g_cp_m : g_rp_m;
    const float* Ps = dir ? g_cp_s : g_rp_s;

    float m = NEG_BIG;
#pragma unroll
    for (int c = 0; c < NBLK; ++c)
        m = fmaxf(m, Pm[c * NB + i]);
    float s = 0.f;
#pragma unroll
    for (int c = 0; c < NBLK; ++c)
        s += Ps[c * NB + i] * __expf(Pm[c * NB + i] - m);
    const float lse = m + logf(s);

    double term = 0.5 * (double)lse;
    if (dir == 0) term -= (double)g_diag[i];

    red[t] = term;
    __syncthreads();
    for (int k = 128; k > 0; k >>= 1) {
        if (t < k) red[t] += red[t + k];
        __syncthreads();
    }
    if (t == 0) {
        g_part[b] = red[0];
        __threadfence();
        const int done = atomicAdd(&g_ticket, 1);
        if (done == 31) {
            double sum = 0.0;
            volatile double* vp = g_part;
            for (int k = 0; k < 32; ++k) sum += vp[k];
            out[0] = (float)(sum / (double)NB);
            g_ticket = 0;    // reset for next graph replay
        }
    }
}

// ---------------------------------------------------------------------------
extern "C" void kernel_launch(void* const* d_in, const int* in_sizes, int n_in,
                              void* d_out, int out_size)
{
    const float* ftir    = (const float*)d_in[0];   // [4096, 512] f32
    const float* raman   = (const float*)d_in[1];   // [4096, 512] f32
    // d_in[2] = labels (int64) — unused
    const float* log_tau = (const float*)d_in[3];   // scalar f32

    cudaFuncSetAttribute(gemm_fused_kernel,
                         cudaFuncAttributeMaxDynamicSharedMemorySize, SM_DYN);

    convert_kernel<<<dim3(NB * ND / (256 * 8), 2), 256>>>(ftir, raman);
    gemm_fused_kernel<<<dim3(NB / BN, NB / BM), GTHREADS, SM_DYN>>>(log_tau);
    combine_final_kernel<<<32, 256>>>((float*)d_out);
}